// round 1
// baseline (speedup 1.0000x reference)
#include <cuda_runtime.h>
#include <cuda_bf16.h>

// Problem: B=64, N=1024, C=192, G=4
//   ori_g = 0.5*(|x| - |x-r_g| + r_g)  ==  clamp(x, 0, r_g)   (r_g >= 0)
//   q_g   = rint(ori_g / (r_g/255)) * (r_g/255)               (0 if r_g==0)
//   sw    = softmax_g(alpha)                                   (4 x 192)
//   ori_activ = sum_g ori_g * sw[g,c] ;  activ = sum_g q_g * sw[g,c]
// Output: concat(ori_activ, activ), each 64*1024*192 f32.

#define C_DIM 192
#define G_DIM 4
#define C4    (C_DIM / 4)   // 48 float4 per channel row
#define TPB   256

__global__ __launch_bounds__(TPB)
void qmod_fused_kernel(const float4* __restrict__ x,
                       const float*  __restrict__ r_in,     // (4,)
                       const float*  __restrict__ alpha,    // (4,192)
                       float4* __restrict__ ori_out,
                       float4* __restrict__ q_out,
                       int n4) {
    __shared__ float sw[G_DIM][C_DIM];

    const int tid = threadIdx.x;

    // --- per-block precompute: softmax over groups for each channel ---
    if (tid < C_DIM) {
        float a0 = alpha[0 * C_DIM + tid];
        float a1 = alpha[1 * C_DIM + tid];
        float a2 = alpha[2 * C_DIM + tid];
        float a3 = alpha[3 * C_DIM + tid];
        float m  = fmaxf(fmaxf(a0, a1), fmaxf(a2, a3));
        float e0 = expf(a0 - m);
        float e1 = expf(a1 - m);
        float e2 = expf(a2 - m);
        float e3 = expf(a3 - m);
        float inv_s = 1.0f / (e0 + e1 + e2 + e3);
        sw[0][tid] = e0 * inv_s;
        sw[1][tid] = e1 * inv_s;
        sw[2][tid] = e2 * inv_s;
        sw[3][tid] = e3 * inv_s;
    }

    // --- per-thread group constants (uniform; broadcast loads, L1-resident) ---
    float rg[G_DIM], bg[G_DIM], ig[G_DIM];
#pragma unroll
    for (int g = 0; g < G_DIM; g++) {
        float r = __ldg(&r_in[g]);
        rg[g] = r;
        bg[g] = r * (1.0f / 255.0f);
        ig[g] = (r > 0.0f) ? (255.0f / r) : 0.0f;  // r==0 -> ori==0 -> q==0 anyway
    }

    __syncthreads();

    const int i = blockIdx.x * TPB + tid;
    if (i >= n4) return;

    const int c4 = i % C4;  // which float4-chunk of the 192-channel row

    const float4 xv = x[i];
    float4 oacc = make_float4(0.f, 0.f, 0.f, 0.f);
    float4 qacc = make_float4(0.f, 0.f, 0.f, 0.f);

#pragma unroll
    for (int g = 0; g < G_DIM; g++) {
        const float4 w = reinterpret_cast<const float4*>(sw[g])[c4];
        const float r   = rg[g];
        const float bs  = bg[g];
        const float inv = ig[g];

        float o0 = fminf(fmaxf(xv.x, 0.0f), r);
        float o1 = fminf(fmaxf(xv.y, 0.0f), r);
        float o2 = fminf(fmaxf(xv.z, 0.0f), r);
        float o3 = fminf(fmaxf(xv.w, 0.0f), r);

        float q0 = rintf(o0 * inv) * bs;
        float q1 = rintf(o1 * inv) * bs;
        float q2 = rintf(o2 * inv) * bs;
        float q3 = rintf(o3 * inv) * bs;

        oacc.x = fmaf(o0, w.x, oacc.x);
        oacc.y = fmaf(o1, w.y, oacc.y);
        oacc.z = fmaf(o2, w.z, oacc.z);
        oacc.w = fmaf(o3, w.w, oacc.w);

        qacc.x = fmaf(q0, w.x, qacc.x);
        qacc.y = fmaf(q1, w.y, qacc.y);
        qacc.z = fmaf(q2, w.z, qacc.z);
        qacc.w = fmaf(q3, w.w, qacc.w);
    }

    ori_out[i] = oacc;
    q_out[i]   = qacc;
}

extern "C" void kernel_launch(void* const* d_in, const int* in_sizes, int n_in,
                              void* d_out, int out_size) {
    const float* x     = (const float*)d_in[0];   // inputs (64,1024,192)
    const float* r     = (const float*)d_in[1];   // groups_range1 (4,)
    const float* alpha = (const float*)d_in[2];   // alpha_activ (4,192)

    const int n_elem = in_sizes[0];               // 12,582,912
    const int n4     = n_elem / 4;                // 3,145,728

    float4* ori_out = (float4*)d_out;             // first half: ori_activ
    float4* q_out   = ori_out + n4;               // second half: activ

    const int blocks = (n4 + TPB - 1) / TPB;
    qmod_fused_kernel<<<blocks, TPB>>>((const float4*)x, r, alpha,
                                       ori_out, q_out, n4);
}

// round 2
// speedup vs baseline: 1.0010x; 1.0010x over previous
#include <cuda_runtime.h>
#include <cuda_bf16.h>

// B=64, N=1024, C=192, G=4
//   ori_g = clamp(x, 0, r_g)
//   q_g   = rint(ori_g * (255/r_g)) * (r_g/255)        (0 if r_g==0)
//   sw    = softmax_g(alpha)  (4 x 192)
//   out   = concat( sum_g ori_g*sw[g,c],  sum_g q_g*sw[g,c] )
//
// Key layout trick: TPB=192 and grid-stride are both divisible by C4=48,
// so each thread's channel-quad is fixed => weights live in registers.

#define C_DIM 192
#define G_DIM 4
#define C4    (C_DIM / 4)     // 48
#define TPB   192
#define NBLK  1024            // 1024*192*16 = 3,145,728 float4 = exact fit

__global__ __launch_bounds__(TPB)
void qmod_fused_kernel(const float4* __restrict__ x,
                       const float*  __restrict__ r_in,
                       const float*  __restrict__ alpha,
                       float4* __restrict__ ori_out,
                       float4* __restrict__ q_out,
                       int n4) {
    __shared__ float sw_o[G_DIM][C_DIM];   // softmax weight
    __shared__ float sw_q[G_DIM][C_DIM];   // softmax weight * (r_g/255)

    const int tid = threadIdx.x;
    const float MAGIC = 12582912.0f;       // 1.5 * 2^23 : RNE rounding constant

    // group constants (uniform broadcast loads)
    float rg[G_DIM], ig[G_DIM];
    float bg[G_DIM];
#pragma unroll
    for (int g = 0; g < G_DIM; g++) {
        float r = __ldg(&r_in[g]);
        rg[g] = r;
        bg[g] = r * (1.0f / 255.0f);
        ig[g] = (r > 0.0f) ? (255.0f / r) : 0.0f;   // r==0 -> o==0 -> q==0
    }

    // per-channel softmax over the 4 groups (one thread per channel; TPB==C_DIM)
    {
        float a0 = alpha[0 * C_DIM + tid];
        float a1 = alpha[1 * C_DIM + tid];
        float a2 = alpha[2 * C_DIM + tid];
        float a3 = alpha[3 * C_DIM + tid];
        float m  = fmaxf(fmaxf(a0, a1), fmaxf(a2, a3));
        float e0 = expf(a0 - m);
        float e1 = expf(a1 - m);
        float e2 = expf(a2 - m);
        float e3 = expf(a3 - m);
        float inv_s = 1.0f / (e0 + e1 + e2 + e3);
        sw_o[0][tid] = e0 * inv_s;  sw_q[0][tid] = e0 * inv_s * bg[0];
        sw_o[1][tid] = e1 * inv_s;  sw_q[1][tid] = e1 * inv_s * bg[1];
        sw_o[2][tid] = e2 * inv_s;  sw_q[2][tid] = e2 * inv_s * bg[2];
        sw_o[3][tid] = e3 * inv_s;  sw_q[3][tid] = e3 * inv_s * bg[3];
    }
    __syncthreads();

    // Because TPB % C4 == 0 and stride % C4 == 0, this thread's channel quad
    // is invariant across the whole grid-stride loop.
    const int c4 = tid % C4;
    float4 wo[G_DIM], wq[G_DIM];
#pragma unroll
    for (int g = 0; g < G_DIM; g++) {
        wo[g] = reinterpret_cast<const float4*>(sw_o[g])[c4];
        wq[g] = reinterpret_cast<const float4*>(sw_q[g])[c4];
    }

    const int stride = gridDim.x * TPB;            // 196,608 : divisible by 48
    int i = blockIdx.x * TPB + tid;

#pragma unroll 4
    for (; i < n4; i += stride) {
        const float4 xv = x[i];
        float4 oacc = make_float4(0.f, 0.f, 0.f, 0.f);
        float4 qacc = make_float4(0.f, 0.f, 0.f, 0.f);

#pragma unroll
        for (int g = 0; g < G_DIM; g++) {
            const float r   = rg[g];
            const float inv = ig[g];

            float o0 = fminf(fmaxf(xv.x, 0.0f), r);
            float o1 = fminf(fmaxf(xv.y, 0.0f), r);
            float o2 = fminf(fmaxf(xv.z, 0.0f), r);
            float o3 = fminf(fmaxf(xv.w, 0.0f), r);

            // RNE round-to-integer via magic constant (o*inv in [0,255])
            float q0 = fmaf(o0, inv, MAGIC) - MAGIC;
            float q1 = fmaf(o1, inv, MAGIC) - MAGIC;
            float q2 = fmaf(o2, inv, MAGIC) - MAGIC;
            float q3 = fmaf(o3, inv, MAGIC) - MAGIC;

            oacc.x = fmaf(o0, wo[g].x, oacc.x);
            oacc.y = fmaf(o1, wo[g].y, oacc.y);
            oacc.z = fmaf(o2, wo[g].z, oacc.z);
            oacc.w = fmaf(o3, wo[g].w, oacc.w);

            qacc.x = fmaf(q0, wq[g].x, qacc.x);
            qacc.y = fmaf(q1, wq[g].y, qacc.y);
            qacc.z = fmaf(q2, wq[g].z, qacc.z);
            qacc.w = fmaf(q3, wq[g].w, qacc.w);
        }

        ori_out[i] = oacc;
        q_out[i]   = qacc;
    }
}

extern "C" void kernel_launch(void* const* d_in, const int* in_sizes, int n_in,
                              void* d_out, int out_size) {
    const float* x     = (const float*)d_in[0];   // inputs (64,1024,192)
    const float* r     = (const float*)d_in[1];   // groups_range1 (4,)
    const float* alpha = (const float*)d_in[2];   // alpha_activ (4,192)

    const int n_elem = in_sizes[0];               // 12,582,912
    const int n4     = n_elem / 4;                // 3,145,728

    float4* ori_out = (float4*)d_out;
    float4* q_out   = ori_out + n4;

    qmod_fused_kernel<<<NBLK, TPB>>>((const float4*)x, r, alpha,
                                     ori_out, q_out, n4);
}

// round 3
// speedup vs baseline: 1.0703x; 1.0692x over previous
#include <cuda_runtime.h>
#include <cuda_bf16.h>

// B=64, N=1024, C=192, G=4
//   ori_g = clamp(x, 0, r_g)
//   q_g   = rint(ori_g * (255/r_g)) * (r_g/255)    (0 if r_g==0)
//   sw    = softmax_g(alpha)  (4 x 192)
//   out   = concat( sum_g ori_g*sw[g,c],  sum_g q_g*sw[g,c] )
//
// TPB=192: block base stride (384) and intra-thread stride (192) are both
// divisible by C4=48, so each thread's channel-quad is fixed -> weights in regs.
// ILP=2 float4 per thread, 8192 blocks: high occupancy + enough MLP.

#define C_DIM 192
#define G_DIM 4
#define C4    (C_DIM / 4)     // 48
#define TPB   192
#define ILP   2
#define NBLK  8192            // 8192 * 192 * 2 = 3,145,728 float4 = exact fit

__global__ __launch_bounds__(TPB)
void qmod_fused_kernel(const float4* __restrict__ x,
                       const float*  __restrict__ r_in,
                       const float*  __restrict__ alpha,
                       float4* __restrict__ ori_out,
                       float4* __restrict__ q_out) {
    __shared__ float sw_o[G_DIM][C_DIM];   // softmax weight
    __shared__ float sw_q[G_DIM][C_DIM];   // softmax weight * (r_g/255)

    const int tid = threadIdx.x;
    const float MAGIC = 12582912.0f;       // 1.5 * 2^23 : RNE rounding constant

    // group constants (uniform broadcast loads)
    float rg[G_DIM], ig[G_DIM];
#pragma unroll
    for (int g = 0; g < G_DIM; g++) {
        float r = __ldg(&r_in[g]);
        rg[g] = r;
        ig[g] = (r > 0.0f) ? (255.0f / r) : 0.0f;   // r==0 -> o==0 -> q==0
    }

    // per-channel softmax over 4 groups (one thread per channel; TPB==C_DIM)
    {
        float a0 = alpha[0 * C_DIM + tid];
        float a1 = alpha[1 * C_DIM + tid];
        float a2 = alpha[2 * C_DIM + tid];
        float a3 = alpha[3 * C_DIM + tid];
        float m  = fmaxf(fmaxf(a0, a1), fmaxf(a2, a3));
        float e0 = expf(a0 - m);
        float e1 = expf(a1 - m);
        float e2 = expf(a2 - m);
        float e3 = expf(a3 - m);
        float inv_s = 1.0f / (e0 + e1 + e2 + e3);
        float w0 = e0 * inv_s, w1 = e1 * inv_s, w2 = e2 * inv_s, w3 = e3 * inv_s;
        sw_o[0][tid] = w0;  sw_q[0][tid] = w0 * (rg[0] * (1.0f / 255.0f));
        sw_o[1][tid] = w1;  sw_q[1][tid] = w1 * (rg[1] * (1.0f / 255.0f));
        sw_o[2][tid] = w2;  sw_q[2][tid] = w2 * (rg[2] * (1.0f / 255.0f));
        sw_o[3][tid] = w3;  sw_q[3][tid] = w3 * (rg[3] * (1.0f / 255.0f));
    }
    __syncthreads();

    // channel-quad-invariant weights -> registers
    const int c4 = tid % C4;
    float4 wo[G_DIM], wq[G_DIM];
#pragma unroll
    for (int g = 0; g < G_DIM; g++) {
        wo[g] = reinterpret_cast<const float4*>(sw_o[g])[c4];
        wq[g] = reinterpret_cast<const float4*>(sw_q[g])[c4];
    }

    const int base = blockIdx.x * (ILP * TPB) + tid;

    // front-batched loads (MLP=2), streaming policy
    const float4 xa = __ldcs(&x[base]);
    const float4 xb = __ldcs(&x[base + TPB]);

    float4 oa, qa, ob, qb;

    // ---- element A, g = 0 (init accumulators with FMUL) ----
    {
        float o0 = fminf(fmaxf(xa.x, 0.0f), rg[0]);
        float o1 = fminf(fmaxf(xa.y, 0.0f), rg[0]);
        float o2 = fminf(fmaxf(xa.z, 0.0f), rg[0]);
        float o3 = fminf(fmaxf(xa.w, 0.0f), rg[0]);
        float t0 = fmaf(o0, ig[0], MAGIC) - MAGIC;
        float t1 = fmaf(o1, ig[0], MAGIC) - MAGIC;
        float t2 = fmaf(o2, ig[0], MAGIC) - MAGIC;
        float t3 = fmaf(o3, ig[0], MAGIC) - MAGIC;
        oa = make_float4(o0 * wo[0].x, o1 * wo[0].y, o2 * wo[0].z, o3 * wo[0].w);
        qa = make_float4(t0 * wq[0].x, t1 * wq[0].y, t2 * wq[0].z, t3 * wq[0].w);
    }
    // ---- element B, g = 0 ----
    {
        float o0 = fminf(fmaxf(xb.x, 0.0f), rg[0]);
        float o1 = fminf(fmaxf(xb.y, 0.0f), rg[0]);
        float o2 = fminf(fmaxf(xb.z, 0.0f), rg[0]);
        float o3 = fminf(fmaxf(xb.w, 0.0f), rg[0]);
        float t0 = fmaf(o0, ig[0], MAGIC) - MAGIC;
        float t1 = fmaf(o1, ig[0], MAGIC) - MAGIC;
        float t2 = fmaf(o2, ig[0], MAGIC) - MAGIC;
        float t3 = fmaf(o3, ig[0], MAGIC) - MAGIC;
        ob = make_float4(o0 * wo[0].x, o1 * wo[0].y, o2 * wo[0].z, o3 * wo[0].w);
        qb = make_float4(t0 * wq[0].x, t1 * wq[0].y, t2 * wq[0].z, t3 * wq[0].w);
    }

#pragma unroll
    for (int g = 1; g < G_DIM; g++) {
        const float r   = rg[g];
        const float inv = ig[g];
        // element A
        {
            float o0 = fminf(fmaxf(xa.x, 0.0f), r);
            float o1 = fminf(fmaxf(xa.y, 0.0f), r);
            float o2 = fminf(fmaxf(xa.z, 0.0f), r);
            float o3 = fminf(fmaxf(xa.w, 0.0f), r);
            float t0 = fmaf(o0, inv, MAGIC) - MAGIC;
            float t1 = fmaf(o1, inv, MAGIC) - MAGIC;
            float t2 = fmaf(o2, inv, MAGIC) - MAGIC;
            float t3 = fmaf(o3, inv, MAGIC) - MAGIC;
            oa.x = fmaf(o0, wo[g].x, oa.x);
            oa.y = fmaf(o1, wo[g].y, oa.y);
            oa.z = fmaf(o2, wo[g].z, oa.z);
            oa.w = fmaf(o3, wo[g].w, oa.w);
            qa.x = fmaf(t0, wq[g].x, qa.x);
            qa.y = fmaf(t1, wq[g].y, qa.y);
            qa.z = fmaf(t2, wq[g].z, qa.z);
            qa.w = fmaf(t3, wq[g].w, qa.w);
        }
        // element B
        {
            float o0 = fminf(fmaxf(xb.x, 0.0f), r);
            float o1 = fminf(fmaxf(xb.y, 0.0f), r);
            float o2 = fminf(fmaxf(xb.z, 0.0f), r);
            float o3 = fminf(fmaxf(xb.w, 0.0f), r);
            float t0 = fmaf(o0, inv, MAGIC) - MAGIC;
            float t1 = fmaf(o1, inv, MAGIC) - MAGIC;
            float t2 = fmaf(o2, inv, MAGIC) - MAGIC;
            float t3 = fmaf(o3, inv, MAGIC) - MAGIC;
            ob.x = fmaf(o0, wo[g].x, ob.x);
            ob.y = fmaf(o1, wo[g].y, ob.y);
            ob.z = fmaf(o2, wo[g].z, ob.z);
            ob.w = fmaf(o3, wo[g].w, ob.w);
            qb.x = fmaf(t0, wq[g].x, qb.x);
            qb.y = fmaf(t1, wq[g].y, qb.y);
            qb.z = fmaf(t2, wq[g].z, qb.z);
            qb.w = fmaf(t3, wq[g].w, qb.w);
        }
    }

    __stcs(&ori_out[base], oa);
    __stcs(&ori_out[base + TPB], ob);
    __stcs(&q_out[base], qa);
    __stcs(&q_out[base + TPB], qb);
}

extern "C" void kernel_launch(void* const* d_in, const int* in_sizes, int n_in,
                              void* d_out, int out_size) {
    const float* x     = (const float*)d_in[0];   // inputs (64,1024,192)
    const float* r     = (const float*)d_in[1];   // groups_range1 (4,)
    const float* alpha = (const float*)d_in[2];   // alpha_activ (4,192)

    const int n_elem = in_sizes[0];               // 12,582,912
    const int n4     = n_elem / 4;                // 3,145,728

    float4* ori_out = (float4*)d_out;
    float4* q_out   = ori_out + n4;

    qmod_fused_kernel<<<NBLK, TPB>>>((const float4*)x, r, alpha,
                                     ori_out, q_out);
}